// round 9
// baseline (speedup 1.0000x reference)
#include <cuda_runtime.h>

#define NB 16
#define NH 16
#define NI 512
#define NE 512
#define IE (NI * NE)
#define JSPLIT 4

// emb partials (device scratch; allocations forbidden)
__device__ float g_embp[JSPLIT][NB * NH * NE];  // 2 MB

// ---------------------------------------------------------------------------
// Kernel 1 (unchanged from R8 best): emb partials.
// g_embp[js][b,h,e] = sum_{j in 128-slice} x[b,j,e]*Wv[h,j,e]
// Block = 8b x 8h x 32e x 128j; 256 threads = 32 e-lanes x 8 j-slices;
// per j: 16 broadcast LDG.32 + 64 FMA into an 8x8 register tile.
// Grid 256 -> one wave at 2 blocks/SM. Also bias-inits the output.
// ---------------------------------------------------------------------------
__global__ __launch_bounds__(256) void emb_kernel(const float* __restrict__ x,
                                                  const float* __restrict__ wv,
                                                  const float* __restrict__ bias,
                                                  float* __restrict__ out) {
    const int t   = threadIdx.x;
    const int bid = blockIdx.x;        // 256 blocks

    // Bias init of the output.
    {
        const int oidx = bid * 256 + t;            // 0 .. 65535
        const float bv = bias[oidx & (NE - 1)];
        out[oidx]         = bv;
        out[oidx + 65536] = bv;
    }

    const int el  = t & 31;            // e lane (coalesced)
    const int sl  = t >> 5;            // j slice (warp id) 0..7
    const int ec  = bid & 15;          // e chunk 0..15
    const int hg  = (bid >> 4) & 1;    // h half
    const int bg  = (bid >> 5) & 1;    // b half
    const int js  = bid >> 6;          // j split 0..3

    const int e = ec * 32 + el;
    const float* xp = x  + bg * 8 * IE + e;
    const float* wp = wv + hg * 8 * IE + e;

    float acc[8][8];
#pragma unroll
    for (int i = 0; i < 8; ++i)
#pragma unroll
        for (int k = 0; k < 8; ++k) acc[i][k] = 0.f;

    const int j0 = js * 128;
#pragma unroll 2
    for (int jj = 0; jj < 16; ++jj) {
        const int joff = (j0 + sl + jj * 8) * NE;
        float xv[8], wv8[8];
#pragma unroll
        for (int i = 0; i < 8; ++i) xv[i]  = __ldg(xp + i * IE + joff);
#pragma unroll
        for (int k = 0; k < 8; ++k) wv8[k] = __ldg(wp + k * IE + joff);
#pragma unroll
        for (int i = 0; i < 8; ++i)
#pragma unroll
            for (int k = 0; k < 8; ++k)
                acc[i][k] = fmaf(xv[i], wv8[k], acc[i][k]);
    }

    __shared__ float red[8][32][32];   // [slice][ik][el] - conflict-free both ways
    const int b0 = bg * 8, h0 = hg * 8;
#pragma unroll
    for (int half = 0; half < 2; ++half) {
        __syncthreads();
#pragma unroll
        for (int ik = 0; ik < 32; ++ik) {
            const int ikf = half * 32 + ik;
            red[sl][ik][el] = acc[ikf >> 3][ikf & 7];
        }
        __syncthreads();
#pragma unroll
        for (int r = 0; r < 4; ++r) {
            const int ik = r * 8 + sl;
            float s = 0.f;
#pragma unroll
            for (int q = 0; q < 8; ++q) s += red[q][ik][el];
            const int ikf = half * 32 + ik;
            const int b = b0 + (ikf >> 3);
            const int h = h0 + (ikf & 7);
            g_embp[js][(b * NH + h) * NE + e] = s;
        }
    }
}

// ---------------------------------------------------------------------------
// Kernel 2: out[m][n] += sum_k emb[m][k]*w[n][k]  (bias already in out)
// M=256, N=512, K=512. Tiles 64m x 64n, split-K=8 (ONE 64-k smem stage)
// -> grid 256: ~1.7 blocks/SM (vs 1 at grid 128 -- the measured occ wall),
// half the per-block critical path, SAME 4x4 micro-tile (16 FMA / 2 LDS.128)
// and SAME 16 MB fold traffic. REDG atomicAdd epilogue.
// ---------------------------------------------------------------------------
__global__ __launch_bounds__(256) void gemm_kernel(const float* __restrict__ w,
                                                   float* __restrict__ out) {
    const int t   = threadIdx.x;
    const int bid = blockIdx.x;        // 256 = 4 mt x 8 nt x 8 kt
    const int kt  = bid & 7;
    const int nt  = (bid >> 3) & 7;
    const int mt  = bid >> 6;
    const int m0 = mt * 64, n0 = nt * 64, k0 = kt * 64;

    __shared__ __align__(16) float sa[64][68];  // [k][m]
    __shared__ __align__(16) float sb[64][68];  // [k][n]

    // A tile: 64m x 64k, folded over the 4 j-split partials
#pragma unroll
    for (int r = 0; r < 4; ++r) {
        const int lin = t + r * 256;        // 1024 float4 slots
        const int row = lin >> 4;           // m 0..63
        const int kq  = (lin & 15) * 4;     // 0..60
        const int aoff = (m0 + row) * NE + k0 + kq;
        float4 a = *(const float4*)&g_embp[0][aoff];
#pragma unroll
        for (int p = 1; p < JSPLIT; ++p) {
            const float4 v = *(const float4*)&g_embp[p][aoff];
            a.x += v.x; a.y += v.y; a.z += v.z; a.w += v.w;
        }
        sa[kq + 0][row] = a.x;
        sa[kq + 1][row] = a.y;
        sa[kq + 2][row] = a.z;
        sa[kq + 3][row] = a.w;
    }
    // B tile: 64n x 64k
#pragma unroll
    for (int r = 0; r < 4; ++r) {
        const int lin = t + r * 256;
        const int row = lin >> 4;           // n 0..63
        const int kq  = (lin & 15) * 4;
        const float4 b4 = *(const float4*)&w[(n0 + row) * NE + k0 + kq];
        sb[kq + 0][row] = b4.x;
        sb[kq + 1][row] = b4.y;
        sb[kq + 2][row] = b4.z;
        sb[kq + 3][row] = b4.w;
    }
    __syncthreads();

    const int tx = t & 15;   // n micro-tile
    const int ty = t >> 4;   // m micro-tile
    float acc[4][4];
#pragma unroll
    for (int i = 0; i < 4; ++i)
#pragma unroll
        for (int j = 0; j < 4; ++j) acc[i][j] = 0.f;

#pragma unroll 8
    for (int kk = 0; kk < 64; ++kk) {
        const float4 av = *(const float4*)&sa[kk][ty * 4];
        const float4 bv = *(const float4*)&sb[kk][tx * 4];
        const float a[4] = {av.x, av.y, av.z, av.w};
        const float b[4] = {bv.x, bv.y, bv.z, bv.w};
#pragma unroll
        for (int i = 0; i < 4; ++i)
#pragma unroll
            for (int j = 0; j < 4; ++j)
                acc[i][j] = fmaf(a[i], b[j], acc[i][j]);
    }

    // Split-K accumulate directly into the bias-initialized output.
#pragma unroll
    for (int i = 0; i < 4; ++i) {
        float* op = &out[(m0 + ty * 4 + i) * NE + n0 + tx * 4];
#pragma unroll
        for (int j = 0; j < 4; ++j)
            atomicAdd(op + j, acc[i][j]);
    }
}

extern "C" void kernel_launch(void* const* d_in, const int* in_sizes, int n_in,
                              void* d_out, int out_size) {
    const float* x    = (const float*)d_in[0];  // [16,1,512,512]
    // d_in[1] = W_q, d_in[2] = W_k: mathematically dead (softmax cols sum to 1)
    const float* wv   = (const float*)d_in[3];  // [1,16,512,512]
    const float* mlpw = (const float*)d_in[4];  // [512,512]
    const float* mlpb = (const float*)d_in[5];  // [512]
    float* out = (float*)d_out;                 // [16,16,512]

    emb_kernel<<<256, 256>>>(x, wv, mlpb, out);
    gemm_kernel<<<256, 256>>>(mlpw, out);
}